// round 1
// baseline (speedup 1.0000x reference)
#include <cuda_runtime.h>
#include <cuda_bf16.h>
#include <cstdint>

#define DD 512
#define NMAX 8192
#define BM 128
#define BN 128
#define BK 32

// Scratch (allocation-free): bf16 copies of x,y + row norms.
__device__ __nv_bfloat16 g_xb[(size_t)NMAX * DD];
__device__ __nv_bfloat16 g_yb[(size_t)NMAX * DD];
__device__ float g_x2[NMAX];
__device__ float g_y2[NMAX];

// One block per row: convert fp32 row -> bf16 and compute sum of squares.
__global__ void prep_kernel(const float* __restrict__ src,
                            __nv_bfloat16* __restrict__ dst,
                            float* __restrict__ norms) {
    const int row = blockIdx.x;
    const int t = threadIdx.x;  // 128 threads, 1 float4 each (512 floats)
    const float4 v = ((const float4*)(src + (size_t)row * DD))[t];
    float s = v.x * v.x + v.y * v.y + v.z * v.z + v.w * v.w;

    __nv_bfloat162 p0 = __floats2bfloat162_rn(v.x, v.y);
    __nv_bfloat162 p1 = __floats2bfloat162_rn(v.z, v.w);
    uint2 pk;
    pk.x = *reinterpret_cast<unsigned*>(&p0);
    pk.y = *reinterpret_cast<unsigned*>(&p1);
    *reinterpret_cast<uint2*>(dst + (size_t)row * DD + t * 4) = pk;

    #pragma unroll
    for (int o = 16; o; o >>= 1) s += __shfl_xor_sync(0xFFFFFFFFu, s, o);
    __shared__ float ws[4];
    if ((t & 31) == 0) ws[t >> 5] = s;
    __syncthreads();
    if (t == 0) norms[row] = ws[0] + ws[1] + ws[2] + ws[3];
}

__device__ __forceinline__ void mma16816(float* c, const uint32_t* a, const uint32_t* b) {
    asm volatile(
        "mma.sync.aligned.m16n8k16.row.col.f32.bf16.bf16.f32 "
        "{%0,%1,%2,%3}, {%4,%5,%6,%7}, {%8,%9}, {%0,%1,%2,%3};\n"
        : "+f"(c[0]), "+f"(c[1]), "+f"(c[2]), "+f"(c[3])
        : "r"(a[0]), "r"(a[1]), "r"(a[2]), "r"(a[3]), "r"(b[0]), "r"(b[1]));
}

// SMEM row stride 40 bf16 = 80 bytes. Fragment LDS bank = (20r + tg) mod 32,
// a permutation over the warp -> conflict-free 32-bit fragment loads.
#define LDA 40

__global__ __launch_bounds__(256, 2)
void rbf_gemm(const float* __restrict__ gamma_p,
              float* __restrict__ out, int Mcols) {
    __shared__ __nv_bfloat16 As[2][BM][LDA];
    __shared__ __nv_bfloat16 Bs[2][BN][LDA];

    const int tid  = threadIdx.x;
    const int lane = tid & 31;
    const int wid  = tid >> 5;
    const int g    = lane >> 2;      // group id 0..7
    const int tg   = lane & 3;       // thread-in-group 0..3
    const int wm   = wid & 3;        // warp m index 0..3 (32 rows each)
    const int wn   = wid >> 2;       // warp n index 0..1 (64 cols each)
    const int bm   = blockIdx.y * BM;
    const int bn   = blockIdx.x * BN;

    // tile = 128 rows x 32 cols bf16 = 512 x 16B chunks; 256 threads, 2 each
    const int r0 = tid >> 2;         // rows 0..63
    const int r1 = r0 + 64;          // rows 64..127
    const int c4 = tid & 3;          // 16B chunk within row (cols c4*8 .. +7)

    const __nv_bfloat16* xbase = g_xb + (size_t)bm * DD;
    const __nv_bfloat16* ybase = g_yb + (size_t)bn * DD;

    float acc[2][8][4];
    #pragma unroll
    for (int mi = 0; mi < 2; mi++)
        #pragma unroll
        for (int ni = 0; ni < 8; ni++)
            #pragma unroll
            for (int k = 0; k < 4; k++) acc[mi][ni][k] = 0.0f;

    const int KT = DD / BK;  // 16

    uint4 la0, la1, lb0, lb1;
    {
        const int k0 = 0;
        la0 = *(const uint4*)(xbase + (size_t)r0 * DD + k0 + c4 * 8);
        la1 = *(const uint4*)(xbase + (size_t)r1 * DD + k0 + c4 * 8);
        lb0 = *(const uint4*)(ybase + (size_t)r0 * DD + k0 + c4 * 8);
        lb1 = *(const uint4*)(ybase + (size_t)r1 * DD + k0 + c4 * 8);
    }
    // STS as 2x uint2 (80B row stride is 8B-aligned, not 16B)
    {
        *(uint2*)&As[0][r0][c4 * 8]     = make_uint2(la0.x, la0.y);
        *(uint2*)&As[0][r0][c4 * 8 + 4] = make_uint2(la0.z, la0.w);
        *(uint2*)&As[0][r1][c4 * 8]     = make_uint2(la1.x, la1.y);
        *(uint2*)&As[0][r1][c4 * 8 + 4] = make_uint2(la1.z, la1.w);
        *(uint2*)&Bs[0][r0][c4 * 8]     = make_uint2(lb0.x, lb0.y);
        *(uint2*)&Bs[0][r0][c4 * 8 + 4] = make_uint2(lb0.z, lb0.w);
        *(uint2*)&Bs[0][r1][c4 * 8]     = make_uint2(lb1.x, lb1.y);
        *(uint2*)&Bs[0][r1][c4 * 8 + 4] = make_uint2(lb1.z, lb1.w);
    }
    __syncthreads();

    for (int kt = 0; kt < KT; kt++) {
        const int buf = kt & 1;
        if (kt + 1 < KT) {
            const int k0 = (kt + 1) * BK;
            la0 = *(const uint4*)(xbase + (size_t)r0 * DD + k0 + c4 * 8);
            la1 = *(const uint4*)(xbase + (size_t)r1 * DD + k0 + c4 * 8);
            lb0 = *(const uint4*)(ybase + (size_t)r0 * DD + k0 + c4 * 8);
            lb1 = *(const uint4*)(ybase + (size_t)r1 * DD + k0 + c4 * 8);
        }

        #pragma unroll
        for (int ks = 0; ks < 2; ks++) {
            const int kk = ks * 16 + 2 * tg;
            uint32_t af[2][4], bfr[8][2];
            #pragma unroll
            for (int mi = 0; mi < 2; mi++) {
                const int r = wm * 32 + mi * 16 + g;
                af[mi][0] = *(const uint32_t*)&As[buf][r][kk];
                af[mi][1] = *(const uint32_t*)&As[buf][r + 8][kk];
                af[mi][2] = *(const uint32_t*)&As[buf][r][kk + 8];
                af[mi][3] = *(const uint32_t*)&As[buf][r + 8][kk + 8];
            }
            #pragma unroll
            for (int ni = 0; ni < 8; ni++) {
                const int r = wn * 64 + ni * 8 + g;
                bfr[ni][0] = *(const uint32_t*)&Bs[buf][r][kk];
                bfr[ni][1] = *(const uint32_t*)&Bs[buf][r][kk + 8];
            }
            #pragma unroll
            for (int mi = 0; mi < 2; mi++)
                #pragma unroll
                for (int ni = 0; ni < 8; ni++)
                    mma16816(acc[mi][ni], af[mi], bfr[ni]);
        }

        if (kt + 1 < KT) {
            __syncthreads();
            const int nb = buf ^ 1;
            *(uint2*)&As[nb][r0][c4 * 8]     = make_uint2(la0.x, la0.y);
            *(uint2*)&As[nb][r0][c4 * 8 + 4] = make_uint2(la0.z, la0.w);
            *(uint2*)&As[nb][r1][c4 * 8]     = make_uint2(la1.x, la1.y);
            *(uint2*)&As[nb][r1][c4 * 8 + 4] = make_uint2(la1.z, la1.w);
            *(uint2*)&Bs[nb][r0][c4 * 8]     = make_uint2(lb0.x, lb0.y);
            *(uint2*)&Bs[nb][r0][c4 * 8 + 4] = make_uint2(lb0.z, lb0.w);
            *(uint2*)&Bs[nb][r1][c4 * 8]     = make_uint2(lb1.x, lb1.y);
            *(uint2*)&Bs[nb][r1][c4 * 8 + 4] = make_uint2(lb1.z, lb1.w);
            __syncthreads();
        }
    }

    // Epilogue: out = exp(-gamma * (x2 + y2 - 2*dot))
    const float gamma = *gamma_p;
    #pragma unroll
    for (int mi = 0; mi < 2; mi++) {
        const int rA = bm + wm * 32 + mi * 16 + g;
        const float x2a = g_x2[rA];
        const float x2b = g_x2[rA + 8];
        #pragma unroll
        for (int ni = 0; ni < 8; ni++) {
            const int cN = bn + wn * 64 + ni * 8 + 2 * tg;
            const float y2a = g_y2[cN];
            const float y2b = g_y2[cN + 1];
            float2 v0, v1;
            v0.x = expf(-gamma * (x2a + y2a - 2.0f * acc[mi][ni][0]));
            v0.y = expf(-gamma * (x2a + y2b - 2.0f * acc[mi][ni][1]));
            v1.x = expf(-gamma * (x2b + y2a - 2.0f * acc[mi][ni][2]));
            v1.y = expf(-gamma * (x2b + y2b - 2.0f * acc[mi][ni][3]));
            *(float2*)&out[(size_t)rA * Mcols + cN]       = v0;
            *(float2*)&out[(size_t)(rA + 8) * Mcols + cN] = v1;
        }
    }
}

extern "C" void kernel_launch(void* const* d_in, const int* in_sizes, int n_in,
                              void* d_out, int out_size) {
    const float* x     = (const float*)d_in[0];
    const float* y     = (const float*)d_in[1];
    const float* gamma = (const float*)d_in[2];
    float* out = (float*)d_out;

    const int N = in_sizes[0] / DD;
    const int M = in_sizes[1] / DD;

    void *xb_p, *yb_p, *x2_p, *y2_p;
    cudaGetSymbolAddress(&xb_p, g_xb);
    cudaGetSymbolAddress(&yb_p, g_yb);
    cudaGetSymbolAddress(&x2_p, g_x2);
    cudaGetSymbolAddress(&y2_p, g_y2);

    prep_kernel<<<N, 128>>>(x, (__nv_bfloat16*)xb_p, (float*)x2_p);
    prep_kernel<<<M, 128>>>(y, (__nv_bfloat16*)yb_p, (float*)y2_p);

    dim3 grid(M / BN, N / BM);
    rbf_gemm<<<grid, 256>>>(gamma, out, M);
}

// round 3
// speedup vs baseline: 1.4280x; 1.4280x over previous
#include <cuda_runtime.h>
#include <cuda.h>
#include <cuda_bf16.h>
#include <cstdint>

#define DD 512
#define NROWS 8192
#define BM 128
#define BN 256
#define KCH 64               // K elems per chunk (128 B rows in SMEM)
#define NCHUNK (DD / KCH)    // 8
#define STAGES 4
#define ABYTES 16384         // 128 rows x 128 B
#define BBYTES 32768         // 256 rows x 128 B
#define STAGE_BYTES (ABYTES + BBYTES)  // 49152

// ---------------- scratch (allocation-free) ----------------
__device__ __nv_bfloat16 g_xb[(size_t)NROWS * DD];
__device__ __nv_bfloat16 g_yb[(size_t)NROWS * DD];
__device__ float g_x2[NROWS];
__device__ float g_y2[NROWS];

// ---------------- PTX helpers ----------------
__device__ __forceinline__ uint32_t smem_u32(const void* p) {
    uint32_t a;
    asm("{ .reg .u64 t; cvta.to.shared.u64 t, %1; cvt.u32.u64 %0, t; }" : "=r"(a) : "l"(p));
    return a;
}
__device__ __forceinline__ uint32_t elect_one_pred() {
    uint32_t p;
    asm volatile("{\n\t.reg .pred p;\n\telect.sync _|p, 0xFFFFFFFF;\n\tselp.b32 %0, 1, 0, p;\n\t}" : "=r"(p));
    return p;
}

#define MBARRIER_INIT(addr, cnt) \
    asm volatile("mbarrier.init.shared.b64 [%0], %1;" :: "r"((uint32_t)(addr)), "r"((uint32_t)(cnt)) : "memory")
#define MBARRIER_EXPECT_TX(addr, bytes) \
    asm volatile("mbarrier.arrive.expect_tx.shared.b64 _, [%0], %1;" :: "r"((uint32_t)(addr)), "r"((uint32_t)(bytes)) : "memory")
#define MBARRIER_ARRIVE(addr) \
    asm volatile("mbarrier.arrive.shared.b64 _, [%0];" :: "r"((uint32_t)(addr)) : "memory")
#define MBARRIER_WAIT_PARITY(addr, parity) do {                                             \
    uint32_t _m = (uint32_t)(addr); uint32_t _p = (uint32_t)(parity); uint32_t _d;          \
    asm volatile("{\n\t.reg .pred p;\n\t"                                                   \
        "mbarrier.try_wait.parity.acquire.cta.shared::cta.b64 p, [%1], %2;\n\t"             \
        "selp.b32 %0, 1, 0, p;\n\t}" : "=r"(_d) : "r"(_m), "r"(_p) : "memory");             \
    if (!_d) {                                                                              \
        asm volatile("{\n\t.reg .pred P1;\n\t"                                              \
            "WL_%=:\n\t"                                                                    \
            "mbarrier.try_wait.parity.acquire.cta.shared::cta.b64 P1, [%0], %1, 0x989680;\n\t" \
            "@P1 bra.uni WD_%=;\n\tbra.uni WL_%=;\n\tWD_%=:\n\t}"                           \
            :: "r"(_m), "r"(_p) : "memory");                                                \
    } } while (0)

#define TMA_LOAD_2D(dst, tmap, cx, cy, mbar) \
    asm volatile("cp.async.bulk.tensor.2d.shared::cta.global.tile.mbarrier::complete_tx::bytes " \
                 "[%0], [%1, {%2, %3}], [%4];" \
                 :: "r"((uint32_t)(dst)), "l"(tmap), "r"((int)(cx)), "r"((int)(cy)), \
                    "r"((uint32_t)(mbar)) : "memory")

#define LDSM_X4(r0, r1, r2, r3, addr) \
    asm volatile("ldmatrix.sync.aligned.m8n8.x4.shared.b16 {%0,%1,%2,%3}, [%4];" \
                 : "=r"(r0), "=r"(r1), "=r"(r2), "=r"(r3) : "r"(addr))

__device__ __forceinline__ void mma16816(float* c, const uint32_t* a, const uint32_t* b) {
    asm volatile(
        "mma.sync.aligned.m16n8k16.row.col.f32.bf16.bf16.f32 "
        "{%0,%1,%2,%3}, {%4,%5,%6,%7}, {%8,%9}, {%0,%1,%2,%3};\n"
        : "+f"(c[0]), "+f"(c[1]), "+f"(c[2]), "+f"(c[3])
        : "r"(a[0]), "r"(a[1]), "r"(a[2]), "r"(a[3]), "r"(b[0]), "r"(b[1]));
}

__device__ __forceinline__ float ex2(float x) {
    float r; asm("ex2.approx.ftz.f32 %0, %1;" : "=f"(r) : "f"(x)); return r;
}

// ---------------- prep: fp32 -> bf16 + row norms ----------------
__global__ void prep_kernel(const float* __restrict__ src,
                            __nv_bfloat16* __restrict__ dst,
                            float* __restrict__ norms) {
    const int row = blockIdx.x;
    const int t = threadIdx.x;  // 128 threads
    const float4 v = ((const float4*)(src + (size_t)row * DD))[t];
    float s = v.x * v.x + v.y * v.y + v.z * v.z + v.w * v.w;

    __nv_bfloat162 p0 = __floats2bfloat162_rn(v.x, v.y);
    __nv_bfloat162 p1 = __floats2bfloat162_rn(v.z, v.w);
    uint2 pk;
    pk.x = *reinterpret_cast<unsigned*>(&p0);
    pk.y = *reinterpret_cast<unsigned*>(&p1);
    *reinterpret_cast<uint2*>(dst + (size_t)row * DD + t * 4) = pk;

    #pragma unroll
    for (int o = 16; o; o >>= 1) s += __shfl_xor_sync(0xFFFFFFFFu, s, o);
    __shared__ float ws[4];
    if ((t & 31) == 0) ws[t >> 5] = s;
    __syncthreads();
    if (t == 0) norms[row] = ws[0] + ws[1] + ws[2] + ws[3];
}

// ---------------- main GEMM: TMA pipeline + mma.sync ----------------
__global__ __launch_bounds__(288, 1)
void rbf_gemm(const __grid_constant__ CUtensorMap tmx,
              const __grid_constant__ CUtensorMap tmy,
              const float* __restrict__ gamma_p,
              float* __restrict__ out) {
    extern __shared__ char dyn_smem[];
    __shared__ __align__(8) uint64_t s_mbar[2 * STAGES];

    const uint32_t sbase = (smem_u32(dyn_smem) + 1023u) & ~1023u;
    const int tid = threadIdx.x, wid = tid >> 5, lane = tid & 31;
    const int bm = blockIdx.y * BM, bn = blockIdx.x * BN;
    const uint32_t mb = smem_u32(s_mbar);
    // full[s] = mb + 8s ; empty[s] = mb + 8*(STAGES+s)

    if (tid == 0) {
        #pragma unroll
        for (int s = 0; s < STAGES; s++) {
            MBARRIER_INIT(mb + 8 * s, 1);               // full: TMA tx
            MBARRIER_INIT(mb + 8 * (STAGES + s), 8);    // empty: 8 compute warps
        }
    }
    __syncthreads();

    if (wid == 8) {
        // ---------- TMA producer warp ----------
        if (elect_one_pred()) {
            int st = 0, ph = 1;
            #pragma unroll 1
            for (int c = 0; c < NCHUNK; c++) {
                MBARRIER_WAIT_PARITY(mb + 8 * (STAGES + st), ph);
                MBARRIER_EXPECT_TX(mb + 8 * st, STAGE_BYTES);
                const uint32_t dst = sbase + st * STAGE_BYTES;
                TMA_LOAD_2D(dst,          &tmx, c * KCH, bm, mb + 8 * st);
                TMA_LOAD_2D(dst + ABYTES, &tmy, c * KCH, bn, mb + 8 * st);
                if (++st == STAGES) { st = 0; ph ^= 1; }
            }
        }
        return;
    }

    // ---------- 8 compute warps: warp = 64(m) x 64(n) of the 128x256 tile ----------
    const int wm = wid & 1;   // 0..1
    const int wn = wid >> 1;  // 0..3

    // A fragment lane geometry (ldmatrix x4 -> one 16x16 m-tile)
    const int rl   = lane & 15;
    const int ahalf = (lane >> 4) & 1;
    const uint32_t swzA = (uint32_t)(rl & 7) << 4;
    uint32_t aRow[4];
    #pragma unroll
    for (int mi = 0; mi < 4; mi++) aRow[mi] = (uint32_t)(wm * 64 + mi * 16 + rl) * 128;
    uint32_t aCol[4];
    #pragma unroll
    for (int ks = 0; ks < 4; ks++) aCol[ks] = ((uint32_t)(ks * 32 + ahalf * 16)) ^ swzA;

    // B fragment lane geometry (ldmatrix x4 -> two 8x16 n-tiles)
    const int rb = (lane & 7) + ((lane >> 4) << 3);
    const int kb = ((lane >> 3) & 1) * 16;
    const uint32_t swzB = (uint32_t)(lane & 7) << 4;
    uint32_t bRow[4];
    #pragma unroll
    for (int nj = 0; nj < 4; nj++) bRow[nj] = (uint32_t)(wn * 64 + nj * 16 + rb) * 128;
    uint32_t bCol[4];
    #pragma unroll
    for (int ks = 0; ks < 4; ks++) bCol[ks] = ((uint32_t)(ks * 32 + kb)) ^ swzB;

    float acc[4][8][4];
    #pragma unroll
    for (int mi = 0; mi < 4; mi++)
        #pragma unroll
        for (int ni = 0; ni < 8; ni++)
            #pragma unroll
            for (int q = 0; q < 4; q++) acc[mi][ni][q] = 0.0f;

    int st = 0, phf = 0;
    #pragma unroll 1
    for (int c = 0; c < NCHUNK; c++) {
        MBARRIER_WAIT_PARITY(mb + 8 * st, phf);
        const uint32_t sa = sbase + st * STAGE_BYTES;
        const uint32_t sb = sa + ABYTES;

        #pragma unroll
        for (int ks = 0; ks < 4; ks++) {
            uint32_t a[4][4], b[8][2];
            #pragma unroll
            for (int mi = 0; mi < 4; mi++)
                LDSM_X4(a[mi][0], a[mi][1], a[mi][2], a[mi][3], sa + aRow[mi] + aCol[ks]);
            #pragma unroll
            for (int nj = 0; nj < 4; nj++)
                LDSM_X4(b[2 * nj][0], b[2 * nj][1], b[2 * nj + 1][0], b[2 * nj + 1][1],
                        sb + bRow[nj] + bCol[ks]);
            #pragma unroll
            for (int mi = 0; mi < 4; mi++)
                #pragma unroll
                for (int ni = 0; ni < 8; ni++)
                    mma16816(acc[mi][ni], a[mi], b[ni]);
        }

        if (elect_one_pred()) MBARRIER_ARRIVE(mb + 8 * (STAGES + st));
        if (++st == STAGES) { st = 0; phf ^= 1; }
    }

    // ---------- epilogue: exp(-g*(x2+y2-2*dot)) = ex2(m2*dot + kx + ky) ----------
    const float g    = *gamma_p;
    const float kneg = -g * 1.4426950408889634f;
    const float m2   =  2.0f * g * 1.4426950408889634f;

    #pragma unroll
    for (int mi = 0; mi < 4; mi++) {
        const int r0 = bm + wm * 64 + mi * 16 + (lane >> 2);
        const float kx0 = kneg * g_x2[r0];
        const float kx1 = kneg * g_x2[r0 + 8];
        #pragma unroll
        for (int ni = 0; ni < 8; ni++) {
            const int col = bn + wn * 64 + ni * 8 + 2 * (lane & 3);
            const float ky0 = kneg * g_y2[col];
            const float ky1 = kneg * g_y2[col + 1];
            float2 v0, v1;
            v0.x = ex2(fmaf(m2, acc[mi][ni][0], kx0 + ky0));
            v0.y = ex2(fmaf(m2, acc[mi][ni][1], kx0 + ky1));
            v1.x = ex2(fmaf(m2, acc[mi][ni][2], kx1 + ky0));
            v1.y = ex2(fmaf(m2, acc[mi][ni][3], kx1 + ky1));
            *reinterpret_cast<float2*>(out + (size_t)r0 * NROWS + col)       = v0;
            *reinterpret_cast<float2*>(out + (size_t)(r0 + 8) * NROWS + col) = v1;
        }
    }
}

// ---------------- host ----------------
typedef CUresult (*EncodeFn)(CUtensorMap*, CUtensorMapDataType, cuuint32_t, void*,
                             const cuuint64_t*, const cuuint64_t*, const cuuint32_t*,
                             const cuuint32_t*, CUtensorMapInterleave, CUtensorMapSwizzle,
                             CUtensorMapL2promotion, CUtensorMapFloatOOBfill);

extern "C" void kernel_launch(void* const* d_in, const int* in_sizes, int n_in,
                              void* d_out, int out_size) {
    const float* x     = (const float*)d_in[0];
    const float* y     = (const float*)d_in[1];
    const float* gamma = (const float*)d_in[2];
    float* out = (float*)d_out;

    const int N = in_sizes[0] / DD;
    const int M = in_sizes[1] / DD;

    void *xb_p, *yb_p, *x2_p, *y2_p;
    cudaGetSymbolAddress(&xb_p, g_xb);
    cudaGetSymbolAddress(&yb_p, g_yb);
    cudaGetSymbolAddress(&x2_p, g_x2);
    cudaGetSymbolAddress(&y2_p, g_y2);

    prep_kernel<<<N, 128>>>(x, (__nv_bfloat16*)xb_p, (float*)x2_p);
    prep_kernel<<<M, 128>>>(y, (__nv_bfloat16*)yb_p, (float*)y2_p);

    void* fp = nullptr;
    cudaDriverEntryPointQueryResult qst;
    cudaGetDriverEntryPoint("cuTensorMapEncodeTiled", &fp, cudaEnableDefault, &qst);
    EncodeFn enc = (EncodeFn)fp;

    alignas(64) CUtensorMap tmx, tmy;
    cuuint64_t gd[2]  = {(cuuint64_t)DD, (cuuint64_t)N};
    cuuint64_t gs[1]  = {(cuuint64_t)(DD * 2)};
    cuuint32_t boxA[2] = {KCH, BM};
    cuuint32_t boxB[2] = {KCH, BN};
    cuuint32_t es[2]  = {1, 1};
    enc(&tmx, CU_TENSOR_MAP_DATA_TYPE_BFLOAT16, 2, xb_p, gd, gs, boxA, es,
        CU_TENSOR_MAP_INTERLEAVE_NONE, CU_TENSOR_MAP_SWIZZLE_128B,
        CU_TENSOR_MAP_L2_PROMOTION_L2_128B, CU_TENSOR_MAP_FLOAT_OOB_FILL_NONE);
    gd[1] = (cuuint64_t)M;
    enc(&tmy, CU_TENSOR_MAP_DATA_TYPE_BFLOAT16, 2, yb_p, gd, gs, boxB, es,
        CU_TENSOR_MAP_INTERLEAVE_NONE, CU_TENSOR_MAP_SWIZZLE_128B,
        CU_TENSOR_MAP_L2_PROMOTION_L2_128B, CU_TENSOR_MAP_FLOAT_OOB_FILL_NONE);

    cudaFuncSetAttribute(rbf_gemm, cudaFuncAttributeMaxDynamicSharedMemorySize,
                         STAGES * STAGE_BYTES + 1024);
    dim3 grid(M / BN, N / BM);  // (32, 64)
    rbf_gemm<<<grid, 288, STAGES * STAGE_BYTES + 1024>>>(tmx, tmy, gamma, out);
}